// round 15
// baseline (speedup 1.0000x reference)
#include <cuda_runtime.h>
#include <cuda_fp16.h>
#include <stdint.h>
#include <math.h>

#define NE    32
#define DH    1024
#define DI    768
#define NT    2048
#define TOPK  8
#define NP    (NT * TOPK)      // 16384 (token, expert) pairs
#define KC    64               // K elems per chunk (64 fp16 = 128 B = SW128 row)
#define NW    (NE * DI * DH)   // elems per weight tensor (25.2M)

// ---------------- scratch (static device globals) ---------------------------
__device__ int   g_off[NE + 1];
__device__ int   g_tok[NP];
__device__ float g_wt[NP];
__device__ int   g_map[NP];
__device__ __align__(16) __half g_h[(size_t)NP * DI];
__device__ __align__(16) float  g_d[(size_t)NP * DH];
__device__ __align__(16) __half w_g[NW], w_u[NW], w_d[NW];
__device__ __align__(16) __half hs_f[NT * DH];

// ---------------- helpers ------------------------------------------------------
#define SWZ(o) ((o) ^ (((o) >> 3) & 0x70))

__device__ __forceinline__ uint32_t smem_u32(const void* p) {
    uint32_t a;
    asm("{ .reg .u64 t; cvta.to.shared.u64 t, %1; cvt.u32.u64 %0, t; }"
        : "=r"(a) : "l"(p));
    return a;
}
__device__ __forceinline__ void ldm4(uint32_t* r, uint32_t a) {
    asm volatile("ldmatrix.sync.aligned.m8n8.x4.shared.b16 {%0,%1,%2,%3}, [%4];"
        : "=r"(r[0]), "=r"(r[1]), "=r"(r[2]), "=r"(r[3]) : "r"(a));
}
__device__ __forceinline__ void mma_h(float* d, const uint32_t* a, const uint32_t* b) {
    asm volatile("mma.sync.aligned.m16n8k16.row.col.f32.f16.f16.f32 "
        "{%0,%1,%2,%3}, {%4,%5,%6,%7}, {%8,%9}, {%0,%1,%2,%3};"
        : "+f"(d[0]), "+f"(d[1]), "+f"(d[2]), "+f"(d[3])
        : "r"(a[0]), "r"(a[1]), "r"(a[2]), "r"(a[3]), "r"(b[0]), "r"(b[1]));
}
__device__ __forceinline__ void cpa16(uint32_t dst, const void* src, uint32_t sz) {
    asm volatile("cp.async.cg.shared.global [%0], [%1], 16, %2;"
                 :: "r"(dst), "l"(src), "r"(sz) : "memory");
}
#define CP_COMMIT() asm volatile("cp.async.commit_group;" ::: "memory")
#define CP_WAIT(n)  asm volatile("cp.async.wait_group %0;" :: "n"(n) : "memory")

__device__ __forceinline__ uint4 pack8h(const float* v) {
    uint32_t r[4];
    #pragma unroll
    for (int p = 0; p < 4; p++) {
        __half2 h2 = __floats2half2_rn(v[2 * p], v[2 * p + 1]);
        r[p] = *reinterpret_cast<uint32_t*>(&h2);
    }
    return make_uint4(r[0], r[1], r[2], r[3]);
}

// ---------------- launch 1: fused routing --------------------------------------
__global__ __launch_bounds__(1024) void k_route(const int* __restrict__ sel,
                                                const float* __restrict__ rw) {
    __shared__ int scnt[NE];
    __shared__ int soff[NE + 1];
    const int tid = threadIdx.x;
    if (tid < NE) scnt[tid] = 0;
    __syncthreads();
    #pragma unroll
    for (int i = tid; i < NP; i += 1024) atomicAdd(&scnt[sel[i]], 1);
    __syncthreads();
    if (tid == 0) {
        int acc = 0;
        soff[0] = 0;
        for (int e = 0; e < NE; e++) { acc += scnt[e]; soff[e + 1] = acc; }
    }
    __syncthreads();
    if (tid <= NE) g_off[tid] = soff[tid];
    if (tid < NE) scnt[tid] = soff[tid];
    __syncthreads();
    #pragma unroll
    for (int i = tid; i < NP; i += 1024) {
        int e = sel[i];
        int p = atomicAdd(&scnt[e], 1);
        g_tok[p] = i / TOPK;
        g_wt[p]  = rw[i];
        g_map[i] = p;
    }
}

// ---------------- launch 2: fused fp32 -> fp16 pre-convert ----------------------
__global__ __launch_bounds__(256) void k_cvt(const float* __restrict__ gate,
        const float* __restrict__ up, const float* __restrict__ down,
        const float* __restrict__ hs) {
    const int nw8 = NW / 8, nh8 = NT * DH / 8;
    int i = blockIdx.x * 256 + threadIdx.x;
    const float* src;
    __half* dst;
    int j;
    if (i < nw8)                { src = gate; dst = w_g;  j = i; }
    else if (i < 2 * nw8)       { src = up;   dst = w_u;  j = i - nw8; }
    else if (i < 3 * nw8)       { src = down; dst = w_d;  j = i - 2 * nw8; }
    else if (i < 3 * nw8 + nh8) { src = hs;   dst = hs_f; j = i - 3 * nw8; }
    else return;
    float v[8];
    float4 a0 = *((const float4*)src + j * 2);
    float4 a1 = *((const float4*)src + j * 2 + 1);
    v[0] = a0.x; v[1] = a0.y; v[2] = a0.z; v[3] = a0.w;
    v[4] = a1.x; v[5] = a1.y; v[6] = a1.z; v[7] = a1.w;
    *(uint4*)(dst + (size_t)j * 8) = pack8h(v);
}

// ---------------- launch 3: GEMM gate+up, SwiGLU epilogue ----------------------
// 128x128 tile; 512 threads (4x4 warps, 32x32 tiles); KC=64 (SW128 rows);
// stage = A G U (3 x 16KB = 48KB); 3 stages = 144KB.
#define TB       16384
#define GU_STAGE (3 * TB)
#define GU_SMEM  (3 * GU_STAGE)       // 144KB
#define GU_NCH   (DH / KC)            // 16

__global__ __launch_bounds__(512, 1)
void k_gateup() {
    const int e    = blockIdx.z;
    const int base = g_off[e];
    const int cnt  = g_off[e + 1] - base;
    const int rowStart = blockIdx.y * 128;
    if (rowStart >= cnt) return;
    const int iStart = blockIdx.x * 128;

    extern __shared__ __align__(1024) char sm[];

    const int tid = threadIdx.x;
    const int wid = tid >> 5, lane = tid & 31;
    const int frow = tid >> 2;
    const int sc   = (tid & 3) * 2;

    const int grow = rowStart + frow;
    const bool av  = (grow < cnt);
    const uint32_t asz = av ? 16u : 0u;
    const int tok  = av ? g_tok[base + grow] : 0;
    const __half* ap = hs_f + (size_t)tok * DH;
    const size_t wrow = ((size_t)e * DI + iStart + frow) * DH;
    const __half* gp = w_g + wrow;
    const __half* up = w_u + wrow;

    const int wm = wid & 3, wn = wid >> 2;
    float accg[2][4][4], accu[2][4][4];
    #pragma unroll
    for (int a = 0; a < 2; a++)
        #pragma unroll
        for (int b = 0; b < 4; b++)
            #pragma unroll
            for (int q = 0; q < 4; q++) { accg[a][b][q] = 0.f; accu[a][b][q] = 0.f; }

    const int a_r = (lane & 15);
    const int a_k = (lane >> 4) * 16;
    const int b_r = ((lane >> 4) & 1) * 8 + (lane & 7);
    const int b_k = ((lane >> 3) & 1) * 16;

    const uint32_t s0 = smem_u32(sm);

    auto fill = [&](int c) {
        const uint32_t sb = s0 + (c % 3) * GU_STAGE;
        const int k0 = c * KC;
        #pragma unroll
        for (int j = 0; j < 2; j++) {
            const uint32_t s = SWZ((uint32_t)(frow * 128 + (sc + j) * 16));
            const int ke = k0 + (sc + j) * 8;
            cpa16(sb + s,          ap + ke, asz);
            cpa16(sb + TB + s,     gp + ke, 16u);
            cpa16(sb + 2 * TB + s, up + ke, 16u);
        }
        CP_COMMIT();
    };

    fill(0);
    fill(1);

    for (int c = 0; c < GU_NCH; c++) {
        CP_WAIT(1);
        __syncthreads();
        if (c + 2 < GU_NCH) fill(c + 2);

        const uint32_t sb = s0 + (c % 3) * GU_STAGE;
        const uint32_t sA = sb;
        const uint32_t sG = sb + TB, sU = sb + 2 * TB;

        #pragma unroll
        for (int ks = 0; ks < 4; ks++) {
            uint32_t ah[2][4];
            #pragma unroll
            for (int mi = 0; mi < 2; mi++) {
                uint32_t off = SWZ((uint32_t)((wm * 32 + mi * 16 + a_r) * 128 + ks * 32 + a_k));
                ldm4(ah[mi], sA + off);
            }
            #pragma unroll
            for (int njp = 0; njp < 2; njp++) {
                uint32_t boff = SWZ((uint32_t)((wn * 32 + njp * 16 + b_r) * 128 + ks * 32 + b_k));
                uint32_t bg[4], bu[4];
                ldm4(bg, sG + boff);
                ldm4(bu, sU + boff);
                #pragma unroll
                for (int mi = 0; mi < 2; mi++)
                    #pragma unroll
                    for (int j = 0; j < 2; j++) {
                        mma_h(accg[mi][njp * 2 + j], ah[mi], &bg[j * 2]);
                        mma_h(accu[mi][njp * 2 + j], ah[mi], &bu[j * 2]);
                    }
            }
        }
    }

    // epilogue: h = w * silu(g) * u -> single fp16
    #pragma unroll
    for (int mi = 0; mi < 2; mi++) {
        #pragma unroll
        for (int h2 = 0; h2 < 2; h2++) {
            const int r = rowStart + wm * 32 + mi * 16 + (lane >> 2) + h2 * 8;
            if (r < cnt) {
                const float w = g_wt[base + r];
                const size_t rb = (size_t)(base + r) * DI + iStart;
                #pragma unroll
                for (int nj = 0; nj < 4; nj++) {
                    const int col = wn * 32 + nj * 8 + (lane & 3) * 2;
                    float g0 = accg[mi][nj][h2 * 2 + 0], g1 = accg[mi][nj][h2 * 2 + 1];
                    float u0 = accu[mi][nj][h2 * 2 + 0], u1 = accu[mi][nj][h2 * 2 + 1];
                    float h0 = w * (g0 / (1.f + __expf(-g0))) * u0;
                    float h1 = w * (g1 / (1.f + __expf(-g1))) * u1;
                    __half2 hh = __floats2half2_rn(h0, h1);
                    *(uint32_t*)&g_h[rb + col] = *reinterpret_cast<uint32_t*>(&hh);
                }
            }
        }
    }
}

// ---------------- launch 4: down projection -> g_d (profiled slot) --------------
// 256 threads, 4x2 warp grid, 32x64 warp tiles (64 acc/thread, <=128 regs);
// stage = A B (2 x 16KB = 32KB); 3 stages = 96KB; 2 CTAs/SM.
#define DN_STAGE (2 * TB)
#define DN_SMEM  (3 * DN_STAGE)       // 96KB
#define DN_NCH   (DI / KC)            // 12

__global__ __launch_bounds__(256, 2)
void k_down() {
    const int e    = blockIdx.z;
    const int base = g_off[e];
    const int cnt  = g_off[e + 1] - base;
    const int rowStart = blockIdx.y * 128;
    if (rowStart >= cnt) return;
    const int hStart = blockIdx.x * 128;

    extern __shared__ __align__(1024) char sm[];

    const int tid = threadIdx.x;
    const int wid = tid >> 5, lane = tid & 31;
    const int frow = tid >> 1;          // 0..127
    const int sc   = (tid & 1) * 4;     // first of 4 16B segments (128B row)

    const int grow = rowStart + frow;
    const bool av  = (grow < cnt);
    const uint32_t asz = av ? 16u : 0u;
    const __half* ap = g_h + (size_t)(av ? base + grow : 0) * DI;
    const size_t wrow = ((size_t)e * DH + hStart + frow) * DI;
    const __half* bp = w_d + wrow;

    const int wm = wid & 3, wn = wid >> 2;   // 4 (M) x 2 (N)
    float acc[2][8][4];                      // 32 rows x 64 cols per warp
    #pragma unroll
    for (int a = 0; a < 2; a++)
        #pragma unroll
        for (int b = 0; b < 8; b++)
            #pragma unroll
            for (int q = 0; q < 4; q++) acc[a][b][q] = 0.f;

    const int a_r = (lane & 15);
    const int a_k = (lane >> 4) * 16;
    const int b_r = ((lane >> 4) & 1) * 8 + (lane & 7);
    const int b_k = ((lane >> 3) & 1) * 16;

    const uint32_t s0 = smem_u32(sm);

    auto fill = [&](int c) {
        const uint32_t sb = s0 + (c % 3) * DN_STAGE;
        const int k0 = c * KC;
        #pragma unroll
        for (int j = 0; j < 4; j++) {
            const uint32_t s = SWZ((uint32_t)(frow * 128 + (sc + j) * 16));
            const int ke = k0 + (sc + j) * 8;
            cpa16(sb + s,      ap + ke, asz);
            cpa16(sb + TB + s, bp + ke, 16u);
        }
        CP_COMMIT();
    };

    fill(0);
    fill(1);

    for (int c = 0; c < DN_NCH; c++) {
        CP_WAIT(1);
        __syncthreads();
        if (c + 2 < DN_NCH) fill(c + 2);

        const uint32_t sb = s0 + (c % 3) * DN_STAGE;
        const uint32_t sA = sb;
        const uint32_t sB = sb + TB;

        #pragma unroll
        for (int ks = 0; ks < 4; ks++) {
            uint32_t ahf[2][4];
            #pragma unroll
            for (int mi = 0; mi < 2; mi++) {
                uint32_t off = SWZ((uint32_t)((wm * 32 + mi * 16 + a_r) * 128 + ks * 32 + a_k));
                ldm4(ahf[mi], sA + off);
            }
            #pragma unroll
            for (int njp = 0; njp < 4; njp++) {
                uint32_t boff = SWZ((uint32_t)((wn * 64 + njp * 16 + b_r) * 128 + ks * 32 + b_k));
                uint32_t bb[4];
                ldm4(bb, sB + boff);
                #pragma unroll
                for (int mi = 0; mi < 2; mi++)
                    #pragma unroll
                    for (int j = 0; j < 2; j++)
                        mma_h(acc[mi][njp * 2 + j], ahf[mi], &bb[j * 2]);
            }
        }
    }

    #pragma unroll
    for (int mi = 0; mi < 2; mi++) {
        #pragma unroll
        for (int h2 = 0; h2 < 2; h2++) {
            const int r = rowStart + wm * 32 + mi * 16 + (lane >> 2) + h2 * 8;
            if (r < cnt) {
                float* dp = &g_d[(size_t)(base + r) * DH + hStart];
                #pragma unroll
                for (int nj = 0; nj < 8; nj++) {
                    const int col = wn * 64 + nj * 8 + (lane & 3) * 2;
                    float2 o;
                    o.x = acc[mi][nj][h2 * 2 + 0];
                    o.y = acc[mi][nj][h2 * 2 + 1];
                    *(float2*)(dp + col) = o;
                }
            }
        }
    }
}

// ---------------- launch 5: deterministic combine -------------------------------
__global__ void k_combine(float* __restrict__ out) {
    const int t = blockIdx.x;
    __shared__ int ps[TOPK];
    if (threadIdx.x < TOPK) ps[threadIdx.x] = g_map[t * TOPK + threadIdx.x];
    __syncthreads();
    const int h = threadIdx.x * 4;
    float4 s = make_float4(0.f, 0.f, 0.f, 0.f);
    #pragma unroll
    for (int k = 0; k < TOPK; k++) {
        float4 v = *(const float4*)&g_d[(size_t)ps[k] * DH + h];
        s.x += v.x; s.y += v.y; s.z += v.z; s.w += v.w;
    }
    *(float4*)&out[(size_t)t * DH + h] = s;
}

// ---------------- launch ---------------------------------------------------------
extern "C" void kernel_launch(void* const* d_in, const int* in_sizes, int n_in,
                              void* d_out, int out_size) {
    const float* hs   = (const float*)d_in[0];
    const float* rw   = (const float*)d_in[1];
    const int*   sel  = (const int*)  d_in[2];
    const float* gate = (const float*)d_in[3];
    const float* up   = (const float*)d_in[4];
    const float* down = (const float*)d_in[5];
    float* out = (float*)d_out;

    k_route<<<1, 1024>>>(sel, rw);

    const int n8 = (3 * NW + NT * DH) / 8;
    k_cvt<<<(n8 + 255) / 256, 256>>>(gate, up, down, hs);

    cudaFuncSetAttribute(k_gateup, cudaFuncAttributeMaxDynamicSharedMemorySize, GU_SMEM);
    cudaFuncSetAttribute(k_down,   cudaFuncAttributeMaxDynamicSharedMemorySize, DN_SMEM);

    dim3 gg(DI / 128, 16, NE);
    k_gateup<<<gg, 512, GU_SMEM>>>();

    // (4) down GEMM — ncu capture slot
    dim3 gd(DH / 128, 16, NE);
    k_down<<<gd, 256, DN_SMEM>>>();

    k_combine<<<NT, 256>>>(out);
}

// round 16
// speedup vs baseline: 1.0458x; 1.0458x over previous
#include <cuda_runtime.h>
#include <cuda_fp16.h>
#include <stdint.h>
#include <math.h>

#define NE    32
#define DH    1024
#define DI    768
#define NT    2048
#define TOPK  8
#define NP    (NT * TOPK)      // 16384 (token, expert) pairs
#define KC    64               // K elems per chunk (64 fp16 = 128 B = SW128 row)
#define NW    (NE * DI * DH)   // elems per weight tensor (25.2M)

// ---------------- scratch (static device globals) ---------------------------
__device__ int   g_off[NE + 1];
__device__ int   g_tok[NP];
__device__ float g_wt[NP];
__device__ int   g_map[NP];
__device__ __align__(16) __half g_h[(size_t)NP * DI];
__device__ __align__(16) __half g_d[(size_t)NP * DH];    // fp16 per-pair output
__device__ __align__(16) __half w_g[NW], w_u[NW], w_d[NW];
__device__ __align__(16) __half hs_f[NT * DH];

// ---------------- helpers ------------------------------------------------------
#define SWZ(o) ((o) ^ (((o) >> 3) & 0x70))

__device__ __forceinline__ uint32_t smem_u32(const void* p) {
    uint32_t a;
    asm("{ .reg .u64 t; cvta.to.shared.u64 t, %1; cvt.u32.u64 %0, t; }"
        : "=r"(a) : "l"(p));
    return a;
}
__device__ __forceinline__ void ldm4(uint32_t* r, uint32_t a) {
    asm volatile("ldmatrix.sync.aligned.m8n8.x4.shared.b16 {%0,%1,%2,%3}, [%4];"
        : "=r"(r[0]), "=r"(r[1]), "=r"(r[2]), "=r"(r[3]) : "r"(a));
}
__device__ __forceinline__ void mma_h(float* d, const uint32_t* a, const uint32_t* b) {
    asm volatile("mma.sync.aligned.m16n8k16.row.col.f32.f16.f16.f32 "
        "{%0,%1,%2,%3}, {%4,%5,%6,%7}, {%8,%9}, {%0,%1,%2,%3};"
        : "+f"(d[0]), "+f"(d[1]), "+f"(d[2]), "+f"(d[3])
        : "r"(a[0]), "r"(a[1]), "r"(a[2]), "r"(a[3]), "r"(b[0]), "r"(b[1]));
}
__device__ __forceinline__ void cpa16(uint32_t dst, const void* src, uint32_t sz) {
    asm volatile("cp.async.cg.shared.global [%0], [%1], 16, %2;"
                 :: "r"(dst), "l"(src), "r"(sz) : "memory");
}
#define CP_COMMIT() asm volatile("cp.async.commit_group;" ::: "memory")
#define CP_WAIT(n)  asm volatile("cp.async.wait_group %0;" :: "n"(n) : "memory")

__device__ __forceinline__ uint4 pack8h(const float* v) {
    uint32_t r[4];
    #pragma unroll
    for (int p = 0; p < 4; p++) {
        __half2 h2 = __floats2half2_rn(v[2 * p], v[2 * p + 1]);
        r[p] = *reinterpret_cast<uint32_t*>(&h2);
    }
    return make_uint4(r[0], r[1], r[2], r[3]);
}

// ---------------- launch 1: fused routing --------------------------------------
__global__ __launch_bounds__(1024) void k_route(const int* __restrict__ sel,
                                                const float* __restrict__ rw) {
    __shared__ int scnt[NE];
    __shared__ int soff[NE + 1];
    const int tid = threadIdx.x;
    if (tid < NE) scnt[tid] = 0;
    __syncthreads();
    #pragma unroll
    for (int i = tid; i < NP; i += 1024) atomicAdd(&scnt[sel[i]], 1);
    __syncthreads();
    if (tid == 0) {
        int acc = 0;
        soff[0] = 0;
        for (int e = 0; e < NE; e++) { acc += scnt[e]; soff[e + 1] = acc; }
    }
    __syncthreads();
    if (tid <= NE) g_off[tid] = soff[tid];
    if (tid < NE) scnt[tid] = soff[tid];
    __syncthreads();
    #pragma unroll
    for (int i = tid; i < NP; i += 1024) {
        int e = sel[i];
        int p = atomicAdd(&scnt[e], 1);
        g_tok[p] = i / TOPK;
        g_wt[p]  = rw[i];
        g_map[i] = p;
    }
}

// ---------------- launch 2: fused fp32 -> fp16 pre-convert ----------------------
__global__ __launch_bounds__(256) void k_cvt(const float* __restrict__ gate,
        const float* __restrict__ up, const float* __restrict__ down,
        const float* __restrict__ hs) {
    const int nw8 = NW / 8, nh8 = NT * DH / 8;
    int i = blockIdx.x * 256 + threadIdx.x;
    const float* src;
    __half* dst;
    int j;
    if (i < nw8)                { src = gate; dst = w_g;  j = i; }
    else if (i < 2 * nw8)       { src = up;   dst = w_u;  j = i - nw8; }
    else if (i < 3 * nw8)       { src = down; dst = w_d;  j = i - 2 * nw8; }
    else if (i < 3 * nw8 + nh8) { src = hs;   dst = hs_f; j = i - 3 * nw8; }
    else return;
    float v[8];
    float4 a0 = *((const float4*)src + j * 2);
    float4 a1 = *((const float4*)src + j * 2 + 1);
    v[0] = a0.x; v[1] = a0.y; v[2] = a0.z; v[3] = a0.w;
    v[4] = a1.x; v[5] = a1.y; v[6] = a1.z; v[7] = a1.w;
    *(uint4*)(dst + (size_t)j * 8) = pack8h(v);
}

// ---------------- launch 3: GEMM gate+up, SwiGLU epilogue ----------------------
// 128x128 tile; 512 threads (4x4 warps, 32x32 tiles); KC=64 (SW128 rows);
// stage = A G U (3 x 16KB = 48KB); 3 stages = 144KB.
#define TB       16384
#define GU_STAGE (3 * TB)
#define GU_SMEM  (3 * GU_STAGE)       // 144KB
#define GU_NCH   (DH / KC)            // 16

__global__ __launch_bounds__(512, 1)
void k_gateup() {
    const int e    = blockIdx.z;
    const int base = g_off[e];
    const int cnt  = g_off[e + 1] - base;
    const int rowStart = blockIdx.y * 128;
    if (rowStart >= cnt) return;
    const int iStart = blockIdx.x * 128;

    extern __shared__ __align__(1024) char sm[];

    const int tid = threadIdx.x;
    const int wid = tid >> 5, lane = tid & 31;
    const int frow = tid >> 2;
    const int sc   = (tid & 3) * 2;

    const int grow = rowStart + frow;
    const bool av  = (grow < cnt);
    const uint32_t asz = av ? 16u : 0u;
    const int tok  = av ? g_tok[base + grow] : 0;
    const __half* ap = hs_f + (size_t)tok * DH;
    const size_t wrow = ((size_t)e * DI + iStart + frow) * DH;
    const __half* gp = w_g + wrow;
    const __half* up = w_u + wrow;

    const int wm = wid & 3, wn = wid >> 2;
    float accg[2][4][4], accu[2][4][4];
    #pragma unroll
    for (int a = 0; a < 2; a++)
        #pragma unroll
        for (int b = 0; b < 4; b++)
            #pragma unroll
            for (int q = 0; q < 4; q++) { accg[a][b][q] = 0.f; accu[a][b][q] = 0.f; }

    const int a_r = (lane & 15);
    const int a_k = (lane >> 4) * 16;
    const int b_r = ((lane >> 4) & 1) * 8 + (lane & 7);
    const int b_k = ((lane >> 3) & 1) * 16;

    const uint32_t s0 = smem_u32(sm);

    auto fill = [&](int c) {
        const uint32_t sb = s0 + (c % 3) * GU_STAGE;
        const int k0 = c * KC;
        #pragma unroll
        for (int j = 0; j < 2; j++) {
            const uint32_t s = SWZ((uint32_t)(frow * 128 + (sc + j) * 16));
            const int ke = k0 + (sc + j) * 8;
            cpa16(sb + s,          ap + ke, asz);
            cpa16(sb + TB + s,     gp + ke, 16u);
            cpa16(sb + 2 * TB + s, up + ke, 16u);
        }
        CP_COMMIT();
    };

    fill(0);
    fill(1);

    for (int c = 0; c < GU_NCH; c++) {
        CP_WAIT(1);
        __syncthreads();
        if (c + 2 < GU_NCH) fill(c + 2);

        const uint32_t sb = s0 + (c % 3) * GU_STAGE;
        const uint32_t sA = sb;
        const uint32_t sG = sb + TB, sU = sb + 2 * TB;

        #pragma unroll
        for (int ks = 0; ks < 4; ks++) {
            uint32_t ah[2][4];
            #pragma unroll
            for (int mi = 0; mi < 2; mi++) {
                uint32_t off = SWZ((uint32_t)((wm * 32 + mi * 16 + a_r) * 128 + ks * 32 + a_k));
                ldm4(ah[mi], sA + off);
            }
            #pragma unroll
            for (int njp = 0; njp < 2; njp++) {
                uint32_t boff = SWZ((uint32_t)((wn * 32 + njp * 16 + b_r) * 128 + ks * 32 + b_k));
                uint32_t bg[4], bu[4];
                ldm4(bg, sG + boff);
                ldm4(bu, sU + boff);
                #pragma unroll
                for (int mi = 0; mi < 2; mi++)
                    #pragma unroll
                    for (int j = 0; j < 2; j++) {
                        mma_h(accg[mi][njp * 2 + j], ah[mi], &bg[j * 2]);
                        mma_h(accu[mi][njp * 2 + j], ah[mi], &bu[j * 2]);
                    }
            }
        }
    }

    // epilogue: h = w * silu(g) * u -> single fp16
    #pragma unroll
    for (int mi = 0; mi < 2; mi++) {
        #pragma unroll
        for (int h2 = 0; h2 < 2; h2++) {
            const int r = rowStart + wm * 32 + mi * 16 + (lane >> 2) + h2 * 8;
            if (r < cnt) {
                const float w = g_wt[base + r];
                const size_t rb = (size_t)(base + r) * DI + iStart;
                #pragma unroll
                for (int nj = 0; nj < 4; nj++) {
                    const int col = wn * 32 + nj * 8 + (lane & 3) * 2;
                    float g0 = accg[mi][nj][h2 * 2 + 0], g1 = accg[mi][nj][h2 * 2 + 1];
                    float u0 = accu[mi][nj][h2 * 2 + 0], u1 = accu[mi][nj][h2 * 2 + 1];
                    float h0 = w * (g0 / (1.f + __expf(-g0))) * u0;
                    float h1 = w * (g1 / (1.f + __expf(-g1))) * u1;
                    __half2 hh = __floats2half2_rn(h0, h1);
                    *(uint32_t*)&g_h[rb + col] = *reinterpret_cast<uint32_t*>(&hh);
                }
            }
        }
    }
}

// ---------------- launch 4: down projection -> g_d (profiled slot) --------------
// R14 config: 512 threads, 4x4 warps, 32x32 tiles; KC=64; stage = A B (32KB);
// 3 stages = 96KB; fp16 output.
#define DN_STAGE (2 * TB)
#define DN_SMEM  (3 * DN_STAGE)       // 96KB
#define DN_NCH   (DI / KC)            // 12

__global__ __launch_bounds__(512, 1)
void k_down() {
    const int e    = blockIdx.z;
    const int base = g_off[e];
    const int cnt  = g_off[e + 1] - base;
    const int rowStart = blockIdx.y * 128;
    if (rowStart >= cnt) return;
    const int hStart = blockIdx.x * 128;

    extern __shared__ __align__(1024) char sm[];

    const int tid = threadIdx.x;
    const int wid = tid >> 5, lane = tid & 31;
    const int frow = tid >> 2;
    const int sc   = (tid & 3) * 2;

    const int grow = rowStart + frow;
    const bool av  = (grow < cnt);
    const uint32_t asz = av ? 16u : 0u;
    const __half* ap = g_h + (size_t)(av ? base + grow : 0) * DI;
    const size_t wrow = ((size_t)e * DH + hStart + frow) * DI;
    const __half* bp = w_d + wrow;

    const int wm = wid & 3, wn = wid >> 2;
    float acc[2][4][4];
    #pragma unroll
    for (int a = 0; a < 2; a++)
        #pragma unroll
        for (int b = 0; b < 4; b++)
            #pragma unroll
            for (int q = 0; q < 4; q++) acc[a][b][q] = 0.f;

    const int a_r = (lane & 15);
    const int a_k = (lane >> 4) * 16;
    const int b_r = ((lane >> 4) & 1) * 8 + (lane & 7);
    const int b_k = ((lane >> 3) & 1) * 16;

    const uint32_t s0 = smem_u32(sm);

    auto fill = [&](int c) {
        const uint32_t sb = s0 + (c % 3) * DN_STAGE;
        const int k0 = c * KC;
        #pragma unroll
        for (int j = 0; j < 2; j++) {
            const uint32_t s = SWZ((uint32_t)(frow * 128 + (sc + j) * 16));
            const int ke = k0 + (sc + j) * 8;
            cpa16(sb + s,      ap + ke, asz);
            cpa16(sb + TB + s, bp + ke, 16u);
        }
        CP_COMMIT();
    };

    fill(0);
    fill(1);

    for (int c = 0; c < DN_NCH; c++) {
        CP_WAIT(1);
        __syncthreads();
        if (c + 2 < DN_NCH) fill(c + 2);

        const uint32_t sb = s0 + (c % 3) * DN_STAGE;
        const uint32_t sA = sb;
        const uint32_t sB = sb + TB;

        #pragma unroll
        for (int ks = 0; ks < 4; ks++) {
            uint32_t ahf[2][4];
            #pragma unroll
            for (int mi = 0; mi < 2; mi++) {
                uint32_t off = SWZ((uint32_t)((wm * 32 + mi * 16 + a_r) * 128 + ks * 32 + a_k));
                ldm4(ahf[mi], sA + off);
            }
            #pragma unroll
            for (int njp = 0; njp < 2; njp++) {
                uint32_t boff = SWZ((uint32_t)((wn * 32 + njp * 16 + b_r) * 128 + ks * 32 + b_k));
                uint32_t bb[4];
                ldm4(bb, sB + boff);
                #pragma unroll
                for (int mi = 0; mi < 2; mi++)
                    #pragma unroll
                    for (int j = 0; j < 2; j++)
                        mma_h(acc[mi][njp * 2 + j], ahf[mi], &bb[j * 2]);
            }
        }
    }

    #pragma unroll
    for (int mi = 0; mi < 2; mi++) {
        #pragma unroll
        for (int h2 = 0; h2 < 2; h2++) {
            const int r = rowStart + wm * 32 + mi * 16 + (lane >> 2) + h2 * 8;
            if (r < cnt) {
                __half* dp = &g_d[(size_t)(base + r) * DH + hStart];
                #pragma unroll
                for (int nj = 0; nj < 4; nj++) {
                    const int col = wn * 32 + nj * 8 + (lane & 3) * 2;
                    __half2 hh = __floats2half2_rn(acc[mi][nj][h2 * 2 + 0],
                                                   acc[mi][nj][h2 * 2 + 1]);
                    *(uint32_t*)(dp + col) = *reinterpret_cast<uint32_t*>(&hh);
                }
            }
        }
    }
}

// ---------------- launch 5: deterministic combine (fp16 partials) ---------------
__global__ void k_combine(float* __restrict__ out) {
    const int t = blockIdx.x;
    __shared__ int ps[TOPK];
    if (threadIdx.x < TOPK) ps[threadIdx.x] = g_map[t * TOPK + threadIdx.x];
    __syncthreads();
    const int h = threadIdx.x * 4;   // 256 threads x 4 halves... use uint2 (4 halves)
    float4 s = make_float4(0.f, 0.f, 0.f, 0.f);
    #pragma unroll
    for (int k = 0; k < TOPK; k++) {
        uint2 v = *(const uint2*)&g_d[(size_t)ps[k] * DH + h];
        __half2 p0 = *reinterpret_cast<__half2*>(&v.x);
        __half2 p1 = *reinterpret_cast<__half2*>(&v.y);
        float2 f0 = __half22float2(p0), f1 = __half22float2(p1);
        s.x += f0.x; s.y += f0.y; s.z += f1.x; s.w += f1.y;
    }
    *(float4*)&out[(size_t)t * DH + h] = s;
}

// ---------------- launch ---------------------------------------------------------
extern "C" void kernel_launch(void* const* d_in, const int* in_sizes, int n_in,
                              void* d_out, int out_size) {
    const float* hs   = (const float*)d_in[0];
    const float* rw   = (const float*)d_in[1];
    const int*   sel  = (const int*)  d_in[2];
    const float* gate = (const float*)d_in[3];
    const float* up   = (const float*)d_in[4];
    const float* down = (const float*)d_in[5];
    float* out = (float*)d_out;

    k_route<<<1, 1024>>>(sel, rw);

    const int n8 = (3 * NW + NT * DH) / 8;
    k_cvt<<<(n8 + 255) / 256, 256>>>(gate, up, down, hs);

    cudaFuncSetAttribute(k_gateup, cudaFuncAttributeMaxDynamicSharedMemorySize, GU_SMEM);
    cudaFuncSetAttribute(k_down,   cudaFuncAttributeMaxDynamicSharedMemorySize, DN_SMEM);

    dim3 gg(DI / 128, 16, NE);
    k_gateup<<<gg, 512, GU_SMEM>>>();

    // (4) down GEMM — ncu capture slot
    dim3 gd(DH / 128, 16, NE);
    k_down<<<gd, 512, DN_SMEM>>>();

    k_combine<<<NT, 256>>>(out);
}

// round 17
// speedup vs baseline: 1.0556x; 1.0094x over previous
#include <cuda_runtime.h>
#include <cuda_fp16.h>
#include <stdint.h>
#include <math.h>

#define NE    32
#define DH    1024
#define DI    768
#define NT    2048
#define TOPK  8
#define NP    (NT * TOPK)      // 16384 (token, expert) pairs
#define KC    64               // K elems per chunk (64 fp16 = 128 B = SW128 row)
#define NW    (NE * DI * DH)   // elems per weight tensor (25.2M)

// ---------------- scratch (static device globals) ---------------------------
__device__ int   g_off[NE + 1];
__device__ int   g_tok[NP];
__device__ float g_wt[NP];
__device__ int   g_map[NP];
__device__ __align__(16) __half g_h[(size_t)NP * DI];
__device__ __align__(16) __half g_d[(size_t)NP * DH];
__device__ __align__(16) __half w_g[NW], w_u[NW], w_d[NW];
__device__ __align__(16) __half hs_f[NT * DH];

// ---------------- helpers ------------------------------------------------------
#define SWZ(o) ((o) ^ (((o) >> 3) & 0x70))

__device__ __forceinline__ uint32_t smem_u32(const void* p) {
    uint32_t a;
    asm("{ .reg .u64 t; cvta.to.shared.u64 t, %1; cvt.u32.u64 %0, t; }"
        : "=r"(a) : "l"(p));
    return a;
}
__device__ __forceinline__ void ldm4(uint32_t* r, uint32_t a) {
    asm volatile("ldmatrix.sync.aligned.m8n8.x4.shared.b16 {%0,%1,%2,%3}, [%4];"
        : "=r"(r[0]), "=r"(r[1]), "=r"(r[2]), "=r"(r[3]) : "r"(a));
}
__device__ __forceinline__ void mma_h(float* d, const uint32_t* a, const uint32_t* b) {
    asm volatile("mma.sync.aligned.m16n8k16.row.col.f32.f16.f16.f32 "
        "{%0,%1,%2,%3}, {%4,%5,%6,%7}, {%8,%9}, {%0,%1,%2,%3};"
        : "+f"(d[0]), "+f"(d[1]), "+f"(d[2]), "+f"(d[3])
        : "r"(a[0]), "r"(a[1]), "r"(a[2]), "r"(a[3]), "r"(b[0]), "r"(b[1]));
}
__device__ __forceinline__ void cpa16(uint32_t dst, const void* src, uint32_t sz) {
    asm volatile("cp.async.cg.shared.global [%0], [%1], 16, %2;"
                 :: "r"(dst), "l"(src), "r"(sz) : "memory");
}
#define CP_COMMIT() asm volatile("cp.async.commit_group;" ::: "memory")
#define CP_WAIT(n)  asm volatile("cp.async.wait_group %0;" :: "n"(n) : "memory")

__device__ __forceinline__ uint4 pack8h(const float* v) {
    uint32_t r[4];
    #pragma unroll
    for (int p = 0; p < 4; p++) {
        __half2 h2 = __floats2half2_rn(v[2 * p], v[2 * p + 1]);
        r[p] = *reinterpret_cast<uint32_t*>(&h2);
    }
    return make_uint4(r[0], r[1], r[2], r[3]);
}
__device__ __forceinline__ void cvt8(const float* src, __half* dst, size_t j) {
    float v[8];
    float4 a0 = *((const float4*)src + j * 2);
    float4 a1 = *((const float4*)src + j * 2 + 1);
    v[0] = a0.x; v[1] = a0.y; v[2] = a0.z; v[3] = a0.w;
    v[4] = a1.x; v[5] = a1.y; v[6] = a1.z; v[7] = a1.w;
    *(uint4*)(dst + j * 8) = pack8h(v);
}

// ---------------- launch 1: route (block 0) + cvt gate/up/hs --------------------
__global__ __launch_bounds__(256) void k_pre(const int* __restrict__ sel,
        const float* __restrict__ rw, const float* __restrict__ gate,
        const float* __restrict__ up, const float* __restrict__ hs) {
    const int tid = threadIdx.x;
    if (blockIdx.x == 0) {
        __shared__ int scnt[NE];
        __shared__ int soff[NE + 1];
        if (tid < NE) scnt[tid] = 0;
        __syncthreads();
        for (int i = tid; i < NP; i += 256) atomicAdd(&scnt[sel[i]], 1);
        __syncthreads();
        if (tid == 0) {
            int acc = 0;
            soff[0] = 0;
            for (int e = 0; e < NE; e++) { acc += scnt[e]; soff[e + 1] = acc; }
        }
        __syncthreads();
        if (tid <= NE) g_off[tid] = soff[tid];
        if (tid < NE) scnt[tid] = soff[tid];
        __syncthreads();
        for (int i = tid; i < NP; i += 256) {
            int e = sel[i];
            int p = atomicAdd(&scnt[e], 1);
            g_tok[p] = i / TOPK;
            g_wt[p]  = rw[i];
            g_map[i] = p;
        }
        return;
    }
    const int nw8 = NW / 8, nh8 = NT * DH / 8;
    int i = (blockIdx.x - 1) * 256 + tid;
    if (i < nw8)                cvt8(gate, w_g, i);
    else if (i < 2 * nw8)       cvt8(up,   w_u, i - nw8);
    else if (i < 2 * nw8 + nh8) cvt8(hs,   hs_f, i - 2 * nw8);
}

// ---------------- launch 2: GEMM gate+up (+ embedded cvt of down weights) -------
// GEMM: z < NE. cvt_d: z in [NE, NE+64) — memory-bound tail blocks that fill
// the DRAM pipe while GEMM blocks own the tensor pipe.
#define TB       16384
#define GU_STAGE (3 * TB)
#define GU_SMEM  (3 * GU_STAGE)       // 144KB
#define GU_NCH   (DH / KC)            // 16
#define CVT_Z    64                   // 64 z-slices x 96 blocks x 4096 elems = NW

__global__ __launch_bounds__(512, 1)
void k_gateup(const float* __restrict__ down) {
    if (blockIdx.z >= NE) {
        // cvt of down-projection weights
        const int bid = (blockIdx.z - NE) * 96 + blockIdx.y * 6 + blockIdx.x;
        const int i = bid * 512 + (int)threadIdx.x;   // octet index
        if (i < NW / 8) cvt8(down, w_d, i);
        return;
    }

    const int e    = blockIdx.z;
    const int base = g_off[e];
    const int cnt  = g_off[e + 1] - base;
    const int rowStart = blockIdx.y * 128;
    if (rowStart >= cnt) return;
    const int iStart = blockIdx.x * 128;

    extern __shared__ __align__(1024) char sm[];

    const int tid = threadIdx.x;
    const int wid = tid >> 5, lane = tid & 31;
    const int frow = tid >> 2;
    const int sc   = (tid & 3) * 2;

    const int grow = rowStart + frow;
    const bool av  = (grow < cnt);
    const uint32_t asz = av ? 16u : 0u;
    const int tok  = av ? g_tok[base + grow] : 0;
    const __half* ap = hs_f + (size_t)tok * DH;
    const size_t wrow = ((size_t)e * DI + iStart + frow) * DH;
    const __half* gp = w_g + wrow;
    const __half* up = w_u + wrow;

    const int wm = wid & 3, wn = wid >> 2;
    float accg[2][4][4], accu[2][4][4];
    #pragma unroll
    for (int a = 0; a < 2; a++)
        #pragma unroll
        for (int b = 0; b < 4; b++)
            #pragma unroll
            for (int q = 0; q < 4; q++) { accg[a][b][q] = 0.f; accu[a][b][q] = 0.f; }

    const int a_r = (lane & 15);
    const int a_k = (lane >> 4) * 16;
    const int b_r = ((lane >> 4) & 1) * 8 + (lane & 7);
    const int b_k = ((lane >> 3) & 1) * 16;

    const uint32_t s0 = smem_u32(sm);

    auto fill = [&](int c) {
        const uint32_t sb = s0 + (c % 3) * GU_STAGE;
        const int k0 = c * KC;
        #pragma unroll
        for (int j = 0; j < 2; j++) {
            const uint32_t s = SWZ((uint32_t)(frow * 128 + (sc + j) * 16));
            const int ke = k0 + (sc + j) * 8;
            cpa16(sb + s,          ap + ke, asz);
            cpa16(sb + TB + s,     gp + ke, 16u);
            cpa16(sb + 2 * TB + s, up + ke, 16u);
        }
        CP_COMMIT();
    };

    fill(0);
    fill(1);

    for (int c = 0; c < GU_NCH; c++) {
        CP_WAIT(1);
        __syncthreads();
        if (c + 2 < GU_NCH) fill(c + 2);

        const uint32_t sb = s0 + (c % 3) * GU_STAGE;
        const uint32_t sA = sb;
        const uint32_t sG = sb + TB, sU = sb + 2 * TB;

        #pragma unroll
        for (int ks = 0; ks < 4; ks++) {
            uint32_t ah[2][4];
            #pragma unroll
            for (int mi = 0; mi < 2; mi++) {
                uint32_t off = SWZ((uint32_t)((wm * 32 + mi * 16 + a_r) * 128 + ks * 32 + a_k));
                ldm4(ah[mi], sA + off);
            }
            #pragma unroll
            for (int njp = 0; njp < 2; njp++) {
                uint32_t boff = SWZ((uint32_t)((wn * 32 + njp * 16 + b_r) * 128 + ks * 32 + b_k));
                uint32_t bg[4], bu[4];
                ldm4(bg, sG + boff);
                ldm4(bu, sU + boff);
                #pragma unroll
                for (int mi = 0; mi < 2; mi++)
                    #pragma unroll
                    for (int j = 0; j < 2; j++) {
                        mma_h(accg[mi][njp * 2 + j], ah[mi], &bg[j * 2]);
                        mma_h(accu[mi][njp * 2 + j], ah[mi], &bu[j * 2]);
                    }
            }
        }
    }

    // epilogue: h = w * silu(g) * u -> single fp16
    #pragma unroll
    for (int mi = 0; mi < 2; mi++) {
        #pragma unroll
        for (int h2 = 0; h2 < 2; h2++) {
            const int r = rowStart + wm * 32 + mi * 16 + (lane >> 2) + h2 * 8;
            if (r < cnt) {
                const float w = g_wt[base + r];
                const size_t rb = (size_t)(base + r) * DI + iStart;
                #pragma unroll
                for (int nj = 0; nj < 4; nj++) {
                    const int col = wn * 32 + nj * 8 + (lane & 3) * 2;
                    float g0 = accg[mi][nj][h2 * 2 + 0], g1 = accg[mi][nj][h2 * 2 + 1];
                    float u0 = accu[mi][nj][h2 * 2 + 0], u1 = accu[mi][nj][h2 * 2 + 1];
                    float h0 = w * (g0 / (1.f + __expf(-g0))) * u0;
                    float h1 = w * (g1 / (1.f + __expf(-g1))) * u1;
                    __half2 hh = __floats2half2_rn(h0, h1);
                    *(uint32_t*)&g_h[rb + col] = *reinterpret_cast<uint32_t*>(&hh);
                }
            }
        }
    }
}

// ---------------- launch 3: down projection -> g_d ------------------------------
#define DN_STAGE (2 * TB)
#define DN_SMEM  (3 * DN_STAGE)       // 96KB
#define DN_NCH   (DI / KC)            // 12

__global__ __launch_bounds__(512, 1)
void k_down() {
    const int e    = blockIdx.z;
    const int base = g_off[e];
    const int cnt  = g_off[e + 1] - base;
    const int rowStart = blockIdx.y * 128;
    if (rowStart >= cnt) return;
    const int hStart = blockIdx.x * 128;

    extern __shared__ __align__(1024) char sm[];

    const int tid = threadIdx.x;
    const int wid = tid >> 5, lane = tid & 31;
    const int frow = tid >> 2;
    const int sc   = (tid & 3) * 2;

    const int grow = rowStart + frow;
    const bool av  = (grow < cnt);
    const uint32_t asz = av ? 16u : 0u;
    const __half* ap = g_h + (size_t)(av ? base + grow : 0) * DI;
    const size_t wrow = ((size_t)e * DH + hStart + frow) * DI;
    const __half* bp = w_d + wrow;

    const int wm = wid & 3, wn = wid >> 2;
    float acc[2][4][4];
    #pragma unroll
    for (int a = 0; a < 2; a++)
        #pragma unroll
        for (int b = 0; b < 4; b++)
            #pragma unroll
            for (int q = 0; q < 4; q++) acc[a][b][q] = 0.f;

    const int a_r = (lane & 15);
    const int a_k = (lane >> 4) * 16;
    const int b_r = ((lane >> 4) & 1) * 8 + (lane & 7);
    const int b_k = ((lane >> 3) & 1) * 16;

    const uint32_t s0 = smem_u32(sm);

    auto fill = [&](int c) {
        const uint32_t sb = s0 + (c % 3) * DN_STAGE;
        const int k0 = c * KC;
        #pragma unroll
        for (int j = 0; j < 2; j++) {
            const uint32_t s = SWZ((uint32_t)(frow * 128 + (sc + j) * 16));
            const int ke = k0 + (sc + j) * 8;
            cpa16(sb + s,      ap + ke, asz);
            cpa16(sb + TB + s, bp + ke, 16u);
        }
        CP_COMMIT();
    };

    fill(0);
    fill(1);

    for (int c = 0; c < DN_NCH; c++) {
        CP_WAIT(1);
        __syncthreads();
        if (c + 2 < DN_NCH) fill(c + 2);

        const uint32_t sb = s0 + (c % 3) * DN_STAGE;
        const uint32_t sA = sb;
        const uint32_t sB = sb + TB;

        #pragma unroll
        for (int ks = 0; ks < 4; ks++) {
            uint32_t ahf[2][4];
            #pragma unroll
            for (int mi = 0; mi < 2; mi++) {
                uint32_t off = SWZ((uint32_t)((wm * 32 + mi * 16 + a_r) * 128 + ks * 32 + a_k));
                ldm4(ahf[mi], sA + off);
            }
            #pragma unroll
            for (int njp = 0; njp < 2; njp++) {
                uint32_t boff = SWZ((uint32_t)((wn * 32 + njp * 16 + b_r) * 128 + ks * 32 + b_k));
                uint32_t bb[4];
                ldm4(bb, sB + boff);
                #pragma unroll
                for (int mi = 0; mi < 2; mi++)
                    #pragma unroll
                    for (int j = 0; j < 2; j++)
                        mma_h(acc[mi][njp * 2 + j], ahf[mi], &bb[j * 2]);
            }
        }
    }

    #pragma unroll
    for (int mi = 0; mi < 2; mi++) {
        #pragma unroll
        for (int h2 = 0; h2 < 2; h2++) {
            const int r = rowStart + wm * 32 + mi * 16 + (lane >> 2) + h2 * 8;
            if (r < cnt) {
                __half* dp = &g_d[(size_t)(base + r) * DH + hStart];
                #pragma unroll
                for (int nj = 0; nj < 4; nj++) {
                    const int col = wn * 32 + nj * 8 + (lane & 3) * 2;
                    __half2 hh = __floats2half2_rn(acc[mi][nj][h2 * 2 + 0],
                                                   acc[mi][nj][h2 * 2 + 1]);
                    *(uint32_t*)(dp + col) = *reinterpret_cast<uint32_t*>(&hh);
                }
            }
        }
    }
}

// ---------------- launch 4: deterministic combine (fp16 partials) ---------------
__global__ void k_combine(float* __restrict__ out) {
    const int t = blockIdx.x;
    __shared__ int ps[TOPK];
    if (threadIdx.x < TOPK) ps[threadIdx.x] = g_map[t * TOPK + threadIdx.x];
    __syncthreads();
    const int h = threadIdx.x * 4;
    float4 s = make_float4(0.f, 0.f, 0.f, 0.f);
    #pragma unroll
    for (int k = 0; k < TOPK; k++) {
        uint2 v = *(const uint2*)&g_d[(size_t)ps[k] * DH + h];
        __half2 p0 = *reinterpret_cast<__half2*>(&v.x);
        __half2 p1 = *reinterpret_cast<__half2*>(&v.y);
        float2 f0 = __half22float2(p0), f1 = __half22float2(p1);
        s.x += f0.x; s.y += f0.y; s.z += f1.x; s.w += f1.y;
    }
    *(float4*)&out[(size_t)t * DH + h] = s;
}

// ---------------- launch ---------------------------------------------------------
extern "C" void kernel_launch(void* const* d_in, const int* in_sizes, int n_in,
                              void* d_out, int out_size) {
    const float* hs   = (const float*)d_in[0];
    const float* rw   = (const float*)d_in[1];
    const int*   sel  = (const int*)  d_in[2];
    const float* gate = (const float*)d_in[3];
    const float* up   = (const float*)d_in[4];
    const float* down = (const float*)d_in[5];
    float* out = (float*)d_out;

    // (1) route + cvt(gate, up, hs)
    const int npre = 1 + (2 * (NW / 8) + (NT * DH / 8) + 255) / 256;
    k_pre<<<npre, 256>>>(sel, rw, gate, up, hs);

    cudaFuncSetAttribute(k_gateup, cudaFuncAttributeMaxDynamicSharedMemorySize, GU_SMEM);
    cudaFuncSetAttribute(k_down,   cudaFuncAttributeMaxDynamicSharedMemorySize, DN_SMEM);

    // (2) gate/up GEMM + embedded cvt(down) in z >= NE
    dim3 gg(DI / 128, 16, NE + CVT_Z);
    k_gateup<<<gg, 512, GU_SMEM>>>(down);

    // (3) down GEMM
    dim3 gd(DH / 128, 16, NE);
    k_down<<<gd, 512, DN_SMEM>>>();

    // (4) combine
    k_combine<<<NT, 256>>>(out);
}